// round 15
// baseline (speedup 1.0000x reference)
#include <cuda_runtime.h>
#include <stdint.h>

#define N1 12800          // 100*128 elements of tm1
#define N2 25600          // 100*256 elements of tm2
#define NT 38400
#define K1 6399           // (N1-1)//2 -> torch lower-median rank
#define K2 12799
#define NBLOCKS 148
#define EPB 260           // 148*260 = 38480 >= 38400
#define CAP 2048          // per-bin bucket capacity
#define SMALL 512         // small-set selection threshold

// 64-bit fused histogram cell: [63:40] count, [39:0] sum of (w*4096 + 65536)
#define HIST_ONE   (1ULL << 40)
#define HIST_MASK  ((1ULL << 40) - 1ULL)
#define W_SCALE    4096.0f
#define W_BIAS     65536LL

// -------- device scratch ----------------------------------------------------
__device__ unsigned long long g_hist[2][2048];       // fused cnt+weight hists
__device__ uint2              g_bkt[2 * 2048 * CAP]; // packed {key, w} buckets
__device__ float4             g_part[NBLOCKS];       // per-block {p1,p2,a1,a2}
__device__ unsigned int       g_arrive;

__device__ __forceinline__ unsigned int mono(unsigned int u) {
    return u ^ ((unsigned int)((int)u >> 31) | 0x80000000u);
}

// re-derive gathered value (fallback only)
__device__ __forceinline__ float regather(int a2, int idx,
                                          const float* c2, const float* c3)
{
    return a2 == 0 ? c2[(size_t)idx * 3136 + 399]
                   : c3[(size_t)idx * 784  + 87];
}

// ------------------- fallback-only helpers (block-wide) -------------------
__device__ unsigned int block_select(const unsigned int* hist, int nb,
                                     unsigned int* warpbuf,
                                     unsigned int* k_sh, unsigned int* sel_sh)
{
    int tid  = threadIdx.x;
    int lane = tid & 31;
    int warp = tid >> 5;
    int bpt  = nb >> 10;
    int base = tid * bpt;

    unsigned int local = 0;
    for (int j = 0; j < bpt; j++) local += hist[base + j];

    unsigned int incl = local;
    #pragma unroll
    for (int o = 1; o < 32; o <<= 1) {
        unsigned int t = __shfl_up_sync(0xffffffffu, incl, o);
        if (lane >= o) incl += t;
    }
    if (lane == 31) warpbuf[warp] = incl;
    __syncthreads();
    if (warp == 0) {
        unsigned int w = warpbuf[lane];
        unsigned int wi = w;
        #pragma unroll
        for (int o = 1; o < 32; o <<= 1) {
            unsigned int t = __shfl_up_sync(0xffffffffu, wi, o);
            if (lane >= o) wi += t;
        }
        warpbuf[lane] = wi - w;
    }
    __syncthreads();

    unsigned int ex = (incl - local) + warpbuf[warp];
    unsigned int k = *k_sh;
    __syncthreads();

    unsigned int c = ex;
    for (int j = 0; j < bpt; j++) {
        unsigned int h = hist[base + j];
        if (k >= c && k < c + h) {
            *sel_sh = (unsigned int)(base + j);
            *k_sh   = k - c;
        }
        c += h;
    }
    __syncthreads();
    return *sel_sh;
}

__device__ float block_sum(float v, float* redf)
{
    int lane = threadIdx.x & 31;
    int warp = threadIdx.x >> 5;
    #pragma unroll
    for (int o = 16; o; o >>= 1) v += __shfl_down_sync(0xffffffffu, v, o);
    if (lane == 0) redf[warp] = v;
    __syncthreads();
    if (warp == 0) {
        float r = redf[lane];
        #pragma unroll
        for (int o = 16; o; o >>= 1) r += __shfl_down_sync(0xffffffffu, r, o);
        if (lane == 0) redf[0] = r;
    }
    __syncthreads();
    float r = redf[0];
    __syncthreads();
    return r;
}

// ---------------------------------------------------------------------------
__global__ void __launch_bounds__(1024) fused_kernel(
    const float* __restrict__ c2,  const float* __restrict__ c3,
    const float* __restrict__ vm1, const float* __restrict__ vm2,
    const float* __restrict__ am1, const float* __restrict__ am2,
    float* __restrict__ out)
{
    __shared__ unsigned int wt_c[2][16];
    __shared__ float        wt_w[2][16];
    __shared__ unsigned int d0_sh[2], kin_sh[2], nc_sh[2], ovf_sh[2];
    __shared__ float        suf_sh[2];
    __shared__ unsigned int sk[2][SMALL];
    __shared__ float        sw[2][SMALL];
    __shared__ unsigned int mkey_sh[2];
    __shared__ float        S_sh[2];
    __shared__ unsigned int fb_hist[2048];
    __shared__ unsigned int warpbuf[32];
    __shared__ float        redf[32];
    __shared__ unsigned int k_sh, sel_sh;
    __shared__ float        shp1[32], shp2[32], sha1[32], sha2[32];
    __shared__ float4       spart[5];
    __shared__ bool         is_last;

    int tid  = threadIdx.x;
    int lane = tid & 31;
    int warp = tid >> 5;

    // ===================== gather ===========================================
    float p1 = 0.f, p2 = 0.f, a1s = 0.f, a2s = 0.f;
    int e = blockIdx.x * EPB + tid;
    if (tid < EPB && e < NT) {
        float t, v, a;
        int arr;
        if (e < N1) {
            t = c2[(size_t)e * 3136 + 399];         // [.,.,7,7]: 7*56+7
            v = vm1[e]; a = am1[e]; arr = 0;
        } else {
            int idx = e - N1;
            t = c3[(size_t)idx * 784 + 87];         // [.,.,3,3]: 3*28+3
            v = vm2[idx]; a = am2[idx]; arr = 1;
        }
        unsigned int key = mono(__float_as_uint(t));
        float w = 1.0f - 2.0f * a;
        unsigned int bin = key >> 21;

        long long wfix = (long long)rintf(w * W_SCALE);
        unsigned long long add = HIST_ONE + (unsigned long long)(wfix + W_BIAS);
        unsigned long long old = atomicAdd(&g_hist[arr][bin], add);
        unsigned int pos = (unsigned int)(old >> 40);
        if (pos < CAP) {
            size_t slot = (size_t)(((unsigned)arr << 11) | bin) * CAP + pos;
            g_bkt[slot] = make_uint2(key, __float_as_uint(w));
        }
        float d = t - v;
        if (arr == 0) { p1 = d * d; a1s = a * a; }
        else          { p2 = d * d; a2s = a * a; }
    }
    #pragma unroll
    for (int o = 16; o; o >>= 1) {
        p1  += __shfl_down_sync(0xffffffffu, p1,  o);
        p2  += __shfl_down_sync(0xffffffffu, p2,  o);
        a1s += __shfl_down_sync(0xffffffffu, a1s, o);
        a2s += __shfl_down_sync(0xffffffffu, a2s, o);
    }
    if (lane == 0) { shp1[warp] = p1; shp2[warp] = p2;
                     sha1[warp] = a1s; sha2[warp] = a2s; }
    __syncthreads();   // orders all bucket stores before tid0's fence

    // ---- block-level reduce: ONE plain float4 store per block (no atomics)
    if (warp == 0) {
        float x1 = shp1[lane], x2 = shp2[lane], x3 = sha1[lane], x4 = sha2[lane];
        #pragma unroll
        for (int o = 16; o; o >>= 1) {
            x1 += __shfl_down_sync(0xffffffffu, x1, o);
            x2 += __shfl_down_sync(0xffffffffu, x2, o);
            x3 += __shfl_down_sync(0xffffffffu, x3, o);
            x4 += __shfl_down_sync(0xffffffffu, x4, o);
        }
        if (lane == 0) {
            g_part[blockIdx.x] = make_float4(x1, x2, x3, x4);
            __threadfence();
            unsigned int r = atomicAdd(&g_arrive, 1u);
            is_last = (r == (unsigned int)(NBLOCKS - 1));
        }
    }
    __syncthreads();
    if (!is_last) return;

    // ===================== finalize: both arrays concurrent =================
    int half    = tid >> 9;          // 0/1 == array index
    int htid    = tid & 511;
    int hwarp   = htid >> 5;         // 0..15
    int arr     = half;
    int binbase = htid << 2;         // 4 bins per thread

    // ---- partial-sum pickup (overlapped with hist trip-1; warps 0..4)
    float4 mypart = make_float4(0.f, 0.f, 0.f, 0.f);
    if (tid < NBLOCKS) mypart = __ldcg(&g_part[tid]);

    // ---- trip 1: load fused hist, decode cnt + weight into registers
    unsigned int cnt[4];
    float        wsm[4];
    #pragma unroll
    for (int j = 0; j < 4; j++) {
        unsigned long long v = __ldcg(&g_hist[arr][binbase + j]);
        unsigned int c = (unsigned int)(v >> 40);
        long long    lw = (long long)(v & HIST_MASK) - (long long)c * W_BIAS;
        cnt[j] = c;
        wsm[j] = (float)lw * (1.0f / W_SCALE);
    }
    // reset hist now (fire-and-forget; values live in registers)
    #pragma unroll
    for (int j = 0; j < 4; j++) g_hist[arr][binbase + j] = 0ULL;

    // reduce partials within warps 0..4 (all lanes converged; zeros padded)
    #pragma unroll
    for (int o = 16; o; o >>= 1) {
        mypart.x += __shfl_down_sync(0xffffffffu, mypart.x, o);
        mypart.y += __shfl_down_sync(0xffffffffu, mypart.y, o);
        mypart.z += __shfl_down_sync(0xffffffffu, mypart.z, o);
        mypart.w += __shfl_down_sync(0xffffffffu, mypart.w, o);
    }
    if (warp < 5 && lane == 0) spart[warp] = mypart;

    // ---- fused level-1 select + suffix-weight (2 barriers)
    unsigned int lc = cnt[0] + cnt[1] + cnt[2] + cnt[3];
    float        lw = wsm[0] + wsm[1] + wsm[2] + wsm[3];
    unsigned int ic = lc; float iw = lw;
    #pragma unroll
    for (int o = 1; o < 32; o <<= 1) {
        unsigned int tc = __shfl_up_sync(0xffffffffu, ic, o);
        float        tw = __shfl_up_sync(0xffffffffu, iw, o);
        if (lane >= o) { ic += tc; iw += tw; }
    }
    if (lane == 31) { wt_c[half][hwarp] = ic; wt_w[half][hwarp] = iw; }
    __syncthreads();   // also publishes spart

    unsigned int woff_c = 0; float woff_w = 0.f, total_w = 0.f;
    #pragma unroll
    for (int w2 = 0; w2 < 16; w2++) {
        unsigned int cc = wt_c[half][w2];
        float        ww = wt_w[half][w2];
        if (w2 < hwarp) { woff_c += cc; woff_w += ww; }
        total_w += ww;
    }
    unsigned int ex  = woff_c + (ic - lc);
    float        exw = woff_w + (iw - lw);
    unsigned int K   = arr ? K2 : K1;
    {
        unsigned int c = ex; float wp = exw;
        #pragma unroll
        for (int j = 0; j < 4; j++) {
            if (K >= c && K < c + cnt[j]) {
                d0_sh[half]  = (unsigned int)(binbase + j);
                kin_sh[half] = K - c;
                suf_sh[half] = total_w - (wp + wsm[j]);
                nc_sh[half]  = cnt[j];
                ovf_sh[half] = (cnt[j] > SMALL) ? 1u : 0u;
            }
            c += cnt[j]; wp += wsm[j];
        }
    }
    __syncthreads();

    if (!(ovf_sh[0] | ovf_sh[1])) {
        // =============== fast path: small-set median, halves concurrent ====
        unsigned int d0  = d0_sh[half];
        unsigned int kin = kin_sh[half];
        unsigned int nc  = nc_sh[half];
        size_t slotbase = (size_t)(((unsigned)arr << 11) | d0) * CAP;

        // trip 2: bucket data (one element per thread; nc <= 512)
        if (htid < (int)nc) {
            uint2 kv = __ldcg(&g_bkt[slotbase + htid]);
            sk[half][htid] = kv.x;
            sw[half][htid] = __uint_as_float(kv.y);
        }
        __syncthreads();
        if (htid < (int)nc) {
            unsigned int mykey = sk[half][htid];
            unsigned int less = 0, eq = 0;
            for (unsigned int j = 0; j < nc; j++) {
                unsigned int kj = sk[half][j];
                less += (kj < mykey);
                eq   += (kj == mykey);
            }
            if (less <= kin && kin < less + eq) mkey_sh[half] = mykey;
        }
        __syncthreads();
        unsigned int mkey = mkey_sh[half];
        float s = (htid < (int)nc && sk[half][htid] >= mkey) ? sw[half][htid] : 0.f;
        #pragma unroll
        for (int o = 16; o; o >>= 1) s += __shfl_down_sync(0xffffffffu, s, o);
        if (lane == 0) wt_w[half][hwarp] = s;
        __syncthreads();
        if (htid == 0) {
            float tsum = 0.f;
            #pragma unroll
            for (int j = 0; j < 16; j++) tsum += wt_w[half][j];
            S_sh[half] = suf_sh[half] + tsum;
        }
    } else {
        // =============== fallback: recompute from inputs (block-wide) ======
        __syncthreads();
        for (int a2 = 0; a2 < 2; a2++) {
            unsigned int fd0 = d0_sh[a2];
            int n = a2 ? N2 : N1;
            const float* am = a2 ? am2 : am1;
            if (tid == 0) k_sh = kin_sh[a2];
            for (int b = tid; b < 2048; b += 1024) fb_hist[b] = 0u;
            __syncthreads();
            for (int j = tid; j < n; j += 1024) {
                unsigned int kk = mono(__float_as_uint(regather(a2, j, c2, c3)));
                if ((kk >> 21) == fd0) atomicAdd(&fb_hist[(kk >> 10) & 2047u], 1u);
            }
            __syncthreads();
            unsigned int d1 = block_select(fb_hist, 2048, warpbuf, &k_sh, &sel_sh);
            unsigned int p21 = (fd0 << 11) | d1;
            fb_hist[tid] = 0u;
            __syncthreads();
            for (int j = tid; j < n; j += 1024) {
                unsigned int kk = mono(__float_as_uint(regather(a2, j, c2, c3)));
                if ((kk >> 10) == p21) atomicAdd(&fb_hist[kk & 1023u], 1u);
            }
            __syncthreads();
            unsigned int d2 = block_select(fb_hist, 1024, warpbuf, &k_sh, &sel_sh);
            unsigned int mkey = (p21 << 10) | d2;
            float s = 0.f;
            for (int j = tid; j < n; j += 1024) {
                unsigned int kk = mono(__float_as_uint(regather(a2, j, c2, c3)));
                if ((kk >> 21) == fd0 && kk >= mkey) s += 1.0f - 2.0f * am[j];
            }
            s = block_sum(s, redf);
            if (tid == 0) S_sh[a2] = suf_sh[a2] + s;
            __syncthreads();
        }
    }
    __syncthreads();

    // ===================== output + remaining state reset ===================
    if (tid == 0) {
        double sp1 = 0.0, sp2 = 0.0, sa1 = 0.0, sa2 = 0.0;
        #pragma unroll
        for (int j = 0; j < 5; j++) {
            sp1 += (double)spart[j].x;
            sp2 += (double)spart[j].y;
            sa1 += (double)spart[j].z;
            sa2 += (double)spart[j].w;
        }
        double p = (sqrt(sp1) + sqrt(sp2)) * (1.0 / 38400.0);
        double q1sq = sa1 + (double)S_sh[0];
        double q2sq = sa2 + (double)S_sh[1];
        double q = (sqrt(q1sq) + sqrt(q2sq)) * (1.0 / 384.0);
        out[0] = (float)p;
        out[1] = (float)q;
        g_arrive = 0u;
    }
}

// ---------------------------------------------------------------------------
extern "C" void kernel_launch(void* const* d_in, const int* in_sizes, int n_in,
                              void* d_out, int out_size)
{
    const float* c2  = (const float*)d_in[0];
    const float* c3  = (const float*)d_in[1];
    const float* vm1 = (const float*)d_in[2];
    const float* vm2 = (const float*)d_in[3];
    const float* am1 = (const float*)d_in[4];
    const float* am2 = (const float*)d_in[5];
    float* out = (float*)d_out;

    fused_kernel<<<NBLOCKS, 1024>>>(c2, c3, vm1, vm2, am1, am2, out);
}

// round 16
// speedup vs baseline: 1.0783x; 1.0783x over previous
#include <cuda_runtime.h>
#include <stdint.h>

#define N1 12800          // 100*128 elements of tm1
#define N2 25600          // 100*256 elements of tm2
#define NT 38400
#define K1 6399           // (N1-1)//2 -> torch lower-median rank
#define K2 12799
#define NBLOCKS 148
#define EPB 260           // 148*260 = 38480 >= 38400
#define CAP 2048          // per-bin bucket capacity
#define SMALL 512         // small-set selection threshold

// 64-bit fused histogram cell: [63:40] count, [39:0] sum of (w*4096 + 65536)
#define HIST_ONE   (1ULL << 40)
#define HIST_MASK  ((1ULL << 40) - 1ULL)
#define W_SCALE    4096.0f
#define W_BIAS     65536LL

// -------- device scratch (reset in-kernel every run) ----------------------
__device__ unsigned long long g_hist[2][2048];       // fused cnt+weight hists
__device__ uint2              g_bkt[2 * 2048 * CAP]; // packed {key, w} buckets
__device__ double             g_sum_p1, g_sum_p2;    // sum (t - vmask)^2
__device__ double             g_sum_a1, g_sum_a2;    // sum amask^2
__device__ unsigned int       g_arrive;

__device__ __forceinline__ unsigned int mono(unsigned int u) {
    return u ^ ((unsigned int)((int)u >> 31) | 0x80000000u);
}

// re-derive gathered value (fallback only)
__device__ __forceinline__ float regather(int a2, int idx,
                                          const float* c2, const float* c3)
{
    return a2 == 0 ? c2[(size_t)idx * 3136 + 399]
                   : c3[(size_t)idx * 784  + 87];
}

// ------------------- fallback-only helpers (block-wide) -------------------
__device__ unsigned int block_select(const unsigned int* hist, int nb,
                                     unsigned int* warpbuf,
                                     unsigned int* k_sh, unsigned int* sel_sh)
{
    int tid  = threadIdx.x;
    int lane = tid & 31;
    int warp = tid >> 5;
    int bpt  = nb >> 10;
    int base = tid * bpt;

    unsigned int local = 0;
    for (int j = 0; j < bpt; j++) local += hist[base + j];

    unsigned int incl = local;
    #pragma unroll
    for (int o = 1; o < 32; o <<= 1) {
        unsigned int t = __shfl_up_sync(0xffffffffu, incl, o);
        if (lane >= o) incl += t;
    }
    if (lane == 31) warpbuf[warp] = incl;
    __syncthreads();
    if (warp == 0) {
        unsigned int w = warpbuf[lane];
        unsigned int wi = w;
        #pragma unroll
        for (int o = 1; o < 32; o <<= 1) {
            unsigned int t = __shfl_up_sync(0xffffffffu, wi, o);
            if (lane >= o) wi += t;
        }
        warpbuf[lane] = wi - w;
    }
    __syncthreads();

    unsigned int ex = (incl - local) + warpbuf[warp];
    unsigned int k = *k_sh;
    __syncthreads();

    unsigned int c = ex;
    for (int j = 0; j < bpt; j++) {
        unsigned int h = hist[base + j];
        if (k >= c && k < c + h) {
            *sel_sh = (unsigned int)(base + j);
            *k_sh   = k - c;
        }
        c += h;
    }
    __syncthreads();
    return *sel_sh;
}

__device__ float block_sum(float v, float* redf)
{
    int lane = threadIdx.x & 31;
    int warp = threadIdx.x >> 5;
    #pragma unroll
    for (int o = 16; o; o >>= 1) v += __shfl_down_sync(0xffffffffu, v, o);
    if (lane == 0) redf[warp] = v;
    __syncthreads();
    if (warp == 0) {
        float r = redf[lane];
        #pragma unroll
        for (int o = 16; o; o >>= 1) r += __shfl_down_sync(0xffffffffu, r, o);
        if (lane == 0) redf[0] = r;
    }
    __syncthreads();
    float r = redf[0];
    __syncthreads();
    return r;
}

// ---------------------------------------------------------------------------
__global__ void __launch_bounds__(1024) fused_kernel(
    const float* __restrict__ c2,  const float* __restrict__ c3,
    const float* __restrict__ vm1, const float* __restrict__ vm2,
    const float* __restrict__ am1, const float* __restrict__ am2,
    float* __restrict__ out)
{
    __shared__ unsigned int wt_c[2][16];
    __shared__ float        wt_w[2][16];
    __shared__ unsigned int d0_sh[2], kin_sh[2], nc_sh[2], ovf_sh[2];
    __shared__ float        suf_sh[2];
    __shared__ unsigned int sk[2][SMALL];
    __shared__ float        sw[2][SMALL];
    __shared__ unsigned int mkey_sh[2];
    __shared__ float        S_sh[2];
    __shared__ unsigned int fb_hist[2048];
    __shared__ unsigned int warpbuf[32];
    __shared__ float        redf[32];
    __shared__ unsigned int k_sh, sel_sh;
    __shared__ float        shp1[32], shp2[32], sha1[32], sha2[32];
    __shared__ bool         is_last;

    int tid  = threadIdx.x;
    int lane = tid & 31;
    int warp = tid >> 5;

    // ===================== gather ===========================================
    float p1 = 0.f, p2 = 0.f, a1s = 0.f, a2s = 0.f;
    int e = blockIdx.x * EPB + tid;
    if (tid < EPB && e < NT) {
        float t, v, a;
        int arr;
        if (e < N1) {
            t = c2[(size_t)e * 3136 + 399];         // [.,.,7,7]: 7*56+7
            v = vm1[e]; a = am1[e]; arr = 0;
        } else {
            int idx = e - N1;
            t = c3[(size_t)idx * 784 + 87];         // [.,.,3,3]: 3*28+3
            v = vm2[idx]; a = am2[idx]; arr = 1;
        }
        unsigned int key = mono(__float_as_uint(t));
        float w = 1.0f - 2.0f * a;
        unsigned int bin = key >> 21;

        long long wfix = (long long)rintf(w * W_SCALE);
        unsigned long long add = HIST_ONE + (unsigned long long)(wfix + W_BIAS);
        unsigned long long old = atomicAdd(&g_hist[arr][bin], add);
        unsigned int pos = (unsigned int)(old >> 40);
        if (pos < CAP) {
            size_t slot = (size_t)(((unsigned)arr << 11) | bin) * CAP + pos;
            g_bkt[slot] = make_uint2(key, __float_as_uint(w));
        }
        float d = t - v;
        if (arr == 0) { p1 = d * d; a1s = a * a; }
        else          { p2 = d * d; a2s = a * a; }
    }
    #pragma unroll
    for (int o = 16; o; o >>= 1) {
        p1  += __shfl_down_sync(0xffffffffu, p1,  o);
        p2  += __shfl_down_sync(0xffffffffu, p2,  o);
        a1s += __shfl_down_sync(0xffffffffu, a1s, o);
        a2s += __shfl_down_sync(0xffffffffu, a2s, o);
    }
    if (lane == 0) { shp1[warp] = p1; shp2[warp] = p2;
                     sha1[warp] = a1s; sha2[warp] = a2s; }
    __syncthreads();   // also orders all bucket stores before tid0's fence

    // ---- block-level reduce: exactly ONE atomic per sum per block
    if (warp == 0) {
        float x1 = shp1[lane], x2 = shp2[lane], x3 = sha1[lane], x4 = sha2[lane];
        #pragma unroll
        for (int o = 16; o; o >>= 1) {
            x1 += __shfl_down_sync(0xffffffffu, x1, o);
            x2 += __shfl_down_sync(0xffffffffu, x2, o);
            x3 += __shfl_down_sync(0xffffffffu, x3, o);
            x4 += __shfl_down_sync(0xffffffffu, x4, o);
        }
        if (lane == 0) {
            atomicAdd(&g_sum_p1, (double)x1);
            atomicAdd(&g_sum_p2, (double)x2);
            atomicAdd(&g_sum_a1, (double)x3);
            atomicAdd(&g_sum_a2, (double)x4);
            __threadfence();
            unsigned int r = atomicAdd(&g_arrive, 1u);
            is_last = (r == (unsigned int)(NBLOCKS - 1));
        }
    }
    __syncthreads();
    if (!is_last) return;

    // ===================== finalize: both arrays concurrent =================
    double sp1 = __ldcg(&g_sum_p1);
    double sp2 = __ldcg(&g_sum_p2);
    double sa1 = __ldcg(&g_sum_a1);
    double sa2 = __ldcg(&g_sum_a2);

    int half    = tid >> 9;          // 0/1 == array index
    int htid    = tid & 511;
    int hwarp   = htid >> 5;         // 0..15
    int arr     = half;
    int binbase = htid << 2;         // 4 bins per thread

    // ---- trip 1: load fused hist, decode cnt + weight into registers
    unsigned int cnt[4];
    float        wsm[4];
    #pragma unroll
    for (int j = 0; j < 4; j++) {
        unsigned long long v = __ldcg(&g_hist[arr][binbase + j]);
        unsigned int c = (unsigned int)(v >> 40);
        long long    lw = (long long)(v & HIST_MASK) - (long long)c * W_BIAS;
        cnt[j] = c;
        wsm[j] = (float)lw * (1.0f / W_SCALE);
    }
    // reset hist now (fire-and-forget; values live in registers)
    #pragma unroll
    for (int j = 0; j < 4; j++) g_hist[arr][binbase + j] = 0ULL;

    // ---- fused level-1 select + suffix-weight (2 barriers)
    unsigned int lc = cnt[0] + cnt[1] + cnt[2] + cnt[3];
    float        lw = wsm[0] + wsm[1] + wsm[2] + wsm[3];
    unsigned int ic = lc; float iw = lw;
    #pragma unroll
    for (int o = 1; o < 32; o <<= 1) {
        unsigned int tc = __shfl_up_sync(0xffffffffu, ic, o);
        float        tw = __shfl_up_sync(0xffffffffu, iw, o);
        if (lane >= o) { ic += tc; iw += tw; }
    }
    if (lane == 31) { wt_c[half][hwarp] = ic; wt_w[half][hwarp] = iw; }
    __syncthreads();

    unsigned int woff_c = 0; float woff_w = 0.f, total_w = 0.f;
    #pragma unroll
    for (int w2 = 0; w2 < 16; w2++) {
        unsigned int cc = wt_c[half][w2];
        float        ww = wt_w[half][w2];
        if (w2 < hwarp) { woff_c += cc; woff_w += ww; }
        total_w += ww;
    }
    unsigned int ex  = woff_c + (ic - lc);
    float        exw = woff_w + (iw - lw);
    unsigned int K   = arr ? K2 : K1;
    {
        unsigned int c = ex; float wp = exw;
        #pragma unroll
        for (int j = 0; j < 4; j++) {
            if (K >= c && K < c + cnt[j]) {
                d0_sh[half]  = (unsigned int)(binbase + j);
                kin_sh[half] = K - c;
                suf_sh[half] = total_w - (wp + wsm[j]);
                nc_sh[half]  = cnt[j];
                ovf_sh[half] = (cnt[j] > SMALL) ? 1u : 0u;
            }
            c += cnt[j]; wp += wsm[j];
        }
    }
    __syncthreads();

    if (!(ovf_sh[0] | ovf_sh[1])) {
        // =============== fast path: small-set median, halves concurrent ====
        unsigned int d0  = d0_sh[half];
        unsigned int kin = kin_sh[half];
        unsigned int nc  = nc_sh[half];
        size_t slotbase = (size_t)(((unsigned)arr << 11) | d0) * CAP;

        // trip 2: bucket data (one element per thread; nc <= 512)
        if (htid < (int)nc) {
            uint2 kv = __ldcg(&g_bkt[slotbase + htid]);
            sk[half][htid] = kv.x;
            sw[half][htid] = __uint_as_float(kv.y);
        }
        __syncthreads();
        if (htid < (int)nc) {
            unsigned int mykey = sk[half][htid];
            unsigned int less = 0, eq = 0;
            for (unsigned int j = 0; j < nc; j++) {
                unsigned int kj = sk[half][j];
                less += (kj < mykey);
                eq   += (kj == mykey);
            }
            if (less <= kin && kin < less + eq) mkey_sh[half] = mykey;
        }
        __syncthreads();
        unsigned int mkey = mkey_sh[half];
        float s = (htid < (int)nc && sk[half][htid] >= mkey) ? sw[half][htid] : 0.f;
        #pragma unroll
        for (int o = 16; o; o >>= 1) s += __shfl_down_sync(0xffffffffu, s, o);
        if (lane == 0) wt_w[half][hwarp] = s;
        __syncthreads();
        if (htid == 0) {
            float tsum = 0.f;
            #pragma unroll
            for (int j = 0; j < 16; j++) tsum += wt_w[half][j];
            S_sh[half] = suf_sh[half] + tsum;
        }
    } else {
        // =============== fallback: recompute from inputs (block-wide) ======
        __syncthreads();
        for (int a2 = 0; a2 < 2; a2++) {
            unsigned int fd0 = d0_sh[a2];
            int n = a2 ? N2 : N1;
            const float* am = a2 ? am2 : am1;
            if (tid == 0) k_sh = kin_sh[a2];
            for (int b = tid; b < 2048; b += 1024) fb_hist[b] = 0u;
            __syncthreads();
            for (int j = tid; j < n; j += 1024) {
                unsigned int kk = mono(__float_as_uint(regather(a2, j, c2, c3)));
                if ((kk >> 21) == fd0) atomicAdd(&fb_hist[(kk >> 10) & 2047u], 1u);
            }
            __syncthreads();
            unsigned int d1 = block_select(fb_hist, 2048, warpbuf, &k_sh, &sel_sh);
            unsigned int p21 = (fd0 << 11) | d1;
            fb_hist[tid] = 0u;
            __syncthreads();
            for (int j = tid; j < n; j += 1024) {
                unsigned int kk = mono(__float_as_uint(regather(a2, j, c2, c3)));
                if ((kk >> 10) == p21) atomicAdd(&fb_hist[kk & 1023u], 1u);
            }
            __syncthreads();
            unsigned int d2 = block_select(fb_hist, 1024, warpbuf, &k_sh, &sel_sh);
            unsigned int mkey = (p21 << 10) | d2;
            float s = 0.f;
            for (int j = tid; j < n; j += 1024) {
                unsigned int kk = mono(__float_as_uint(regather(a2, j, c2, c3)));
                if ((kk >> 21) == fd0 && kk >= mkey) s += 1.0f - 2.0f * am[j];
            }
            s = block_sum(s, redf);
            if (tid == 0) S_sh[a2] = suf_sh[a2] + s;
            __syncthreads();
        }
    }
    __syncthreads();

    // ===================== output + remaining state reset ===================
    if (tid == 0) {
        double p = (sqrt(sp1) + sqrt(sp2)) * (1.0 / 38400.0);
        double q1sq = sa1 + (double)S_sh[0];
        double q2sq = sa2 + (double)S_sh[1];
        double q = (sqrt(q1sq) + sqrt(q2sq)) * (1.0 / 384.0);
        out[0] = (float)p;
        out[1] = (float)q;
        g_sum_p1 = 0.0; g_sum_p2 = 0.0;
        g_sum_a1 = 0.0; g_sum_a2 = 0.0;
        g_arrive = 0u;
    }
}

// ---------------------------------------------------------------------------
extern "C" void kernel_launch(void* const* d_in, const int* in_sizes, int n_in,
                              void* d_out, int out_size)
{
    const float* c2  = (const float*)d_in[0];
    const float* c3  = (const float*)d_in[1];
    const float* vm1 = (const float*)d_in[2];
    const float* vm2 = (const float*)d_in[3];
    const float* am1 = (const float*)d_in[4];
    const float* am2 = (const float*)d_in[5];
    float* out = (float*)d_out;

    fused_kernel<<<NBLOCKS, 1024>>>(c2, c3, vm1, vm2, am1, am2, out);
}

// round 17
// speedup vs baseline: 1.1045x; 1.0243x over previous
#include <cuda_runtime.h>
#include <stdint.h>

#define N1 12800          // 100*128 elements of tm1
#define N2 25600          // 100*256 elements of tm2
#define NT 38400
#define K1 6399           // (N1-1)//2 -> torch lower-median rank
#define K2 12799
#define NBLOCKS 148
#define EPB 260           // 148*260 = 38480 >= 38400
#define CAP 2048          // per-bin bucket capacity
#define SMALL 512         // small-set selection threshold

// 64-bit fused histogram cell: [63:40] count, [39:0] sum of (w*4096 + 65536)
#define HIST_ONE   (1ULL << 40)
#define HIST_MASK  ((1ULL << 40) - 1ULL)
#define W_SCALE    4096.0f
#define W_BIAS     65536LL

// -------- device scratch (reset in-kernel every run) ----------------------
__device__ unsigned long long g_hist[2][2048];       // fused cnt+weight hists
__device__ uint2              g_bkt[2 * 2048 * CAP]; // packed {key, w} buckets
__device__ double             g_sum_p1, g_sum_p2;    // sum (t - vmask)^2
__device__ double             g_sum_a1, g_sum_a2;    // sum amask^2
__device__ unsigned int       g_arrive;

__device__ __forceinline__ unsigned int mono(unsigned int u) {
    return u ^ ((unsigned int)((int)u >> 31) | 0x80000000u);
}

// re-derive gathered value (fallback only)
__device__ __forceinline__ float regather(int a2, int idx,
                                          const float* c2, const float* c3)
{
    return a2 == 0 ? c2[(size_t)idx * 3136 + 399]
                   : c3[(size_t)idx * 784  + 87];
}

// ------------------- fallback-only helpers (block-wide) -------------------
__device__ unsigned int block_select(const unsigned int* hist, int nb,
                                     unsigned int* warpbuf,
                                     unsigned int* k_sh, unsigned int* sel_sh)
{
    int tid  = threadIdx.x;
    int lane = tid & 31;
    int warp = tid >> 5;
    int bpt  = nb >> 10;
    int base = tid * bpt;

    unsigned int local = 0;
    for (int j = 0; j < bpt; j++) local += hist[base + j];

    unsigned int incl = local;
    #pragma unroll
    for (int o = 1; o < 32; o <<= 1) {
        unsigned int t = __shfl_up_sync(0xffffffffu, incl, o);
        if (lane >= o) incl += t;
    }
    if (lane == 31) warpbuf[warp] = incl;
    __syncthreads();
    if (warp == 0) {
        unsigned int w = warpbuf[lane];
        unsigned int wi = w;
        #pragma unroll
        for (int o = 1; o < 32; o <<= 1) {
            unsigned int t = __shfl_up_sync(0xffffffffu, wi, o);
            if (lane >= o) wi += t;
        }
        warpbuf[lane] = wi - w;
    }
    __syncthreads();

    unsigned int ex = (incl - local) + warpbuf[warp];
    unsigned int k = *k_sh;
    __syncthreads();

    unsigned int c = ex;
    for (int j = 0; j < bpt; j++) {
        unsigned int h = hist[base + j];
        if (k >= c && k < c + h) {
            *sel_sh = (unsigned int)(base + j);
            *k_sh   = k - c;
        }
        c += h;
    }
    __syncthreads();
    return *sel_sh;
}

__device__ float block_sum(float v, float* redf)
{
    int lane = threadIdx.x & 31;
    int warp = threadIdx.x >> 5;
    #pragma unroll
    for (int o = 16; o; o >>= 1) v += __shfl_down_sync(0xffffffffu, v, o);
    if (lane == 0) redf[warp] = v;
    __syncthreads();
    if (warp == 0) {
        float r = redf[lane];
        #pragma unroll
        for (int o = 16; o; o >>= 1) r += __shfl_down_sync(0xffffffffu, r, o);
        if (lane == 0) redf[0] = r;
    }
    __syncthreads();
    float r = redf[0];
    __syncthreads();
    return r;
}

// ---------------------------------------------------------------------------
__global__ void __launch_bounds__(1024) fused_kernel(
    const float* __restrict__ c2,  const float* __restrict__ c3,
    const float* __restrict__ vm1, const float* __restrict__ vm2,
    const float* __restrict__ am1, const float* __restrict__ am2,
    float* __restrict__ out)
{
    __shared__ unsigned int wt_c[2][16];
    __shared__ float        wt_w[2][16];
    __shared__ unsigned int d0_sh[2], kin_sh[2], nc_sh[2], ovf_sh[2];
    __shared__ float        suf_sh[2];
    __shared__ unsigned int sk[2][SMALL];
    __shared__ float        sw[2][SMALL];
    __shared__ unsigned int mkey_sh[2];
    __shared__ float        S_sh[2];
    __shared__ unsigned int fb_hist[2048];
    __shared__ unsigned int warpbuf[32];
    __shared__ float        redf[32];
    __shared__ unsigned int k_sh, sel_sh;
    __shared__ float        shp1[32], shp2[32], sha1[32], sha2[32];
    __shared__ bool         is_last;

    int tid  = threadIdx.x;
    int lane = tid & 31;
    int warp = tid >> 5;

    // ===================== gather ===========================================
    float p1 = 0.f, p2 = 0.f, a1s = 0.f, a2s = 0.f;
    int e = blockIdx.x * EPB + tid;
    if (tid < EPB && e < NT) {
        float t, v, a;
        int arr;
        if (e < N1) {
            t = c2[(size_t)e * 3136 + 399];         // [.,.,7,7]: 7*56+7
            v = vm1[e]; a = am1[e]; arr = 0;
        } else {
            int idx = e - N1;
            t = c3[(size_t)idx * 784 + 87];         // [.,.,3,3]: 3*28+3
            v = vm2[idx]; a = am2[idx]; arr = 1;
        }
        unsigned int key = mono(__float_as_uint(t));
        float w = 1.0f - 2.0f * a;
        unsigned int bin = key >> 21;

        long long wfix = (long long)rintf(w * W_SCALE);
        unsigned long long add = HIST_ONE + (unsigned long long)(wfix + W_BIAS);
        unsigned long long old = atomicAdd(&g_hist[arr][bin], add);
        unsigned int pos = (unsigned int)(old >> 40);
        if (pos < CAP) {
            size_t slot = (size_t)(((unsigned)arr << 11) | bin) * CAP + pos;
            g_bkt[slot] = make_uint2(key, __float_as_uint(w));
        }
        float d = t - v;
        if (arr == 0) { p1 = d * d; a1s = a * a; }
        else          { p2 = d * d; a2s = a * a; }
    }
    #pragma unroll
    for (int o = 16; o; o >>= 1) {
        p1  += __shfl_down_sync(0xffffffffu, p1,  o);
        p2  += __shfl_down_sync(0xffffffffu, p2,  o);
        a1s += __shfl_down_sync(0xffffffffu, a1s, o);
        a2s += __shfl_down_sync(0xffffffffu, a2s, o);
    }
    if (lane == 0) { shp1[warp] = p1; shp2[warp] = p2;
                     sha1[warp] = a1s; sha2[warp] = a2s; }
    __syncthreads();   // also orders all bucket stores before tid0's fence

    // ---- block-level reduce: exactly ONE atomic per sum per block
    if (warp == 0) {
        float x1 = shp1[lane], x2 = shp2[lane], x3 = sha1[lane], x4 = sha2[lane];
        #pragma unroll
        for (int o = 16; o; o >>= 1) {
            x1 += __shfl_down_sync(0xffffffffu, x1, o);
            x2 += __shfl_down_sync(0xffffffffu, x2, o);
            x3 += __shfl_down_sync(0xffffffffu, x3, o);
            x4 += __shfl_down_sync(0xffffffffu, x4, o);
        }
        if (lane == 0) {
            atomicAdd(&g_sum_p1, (double)x1);
            atomicAdd(&g_sum_p2, (double)x2);
            atomicAdd(&g_sum_a1, (double)x3);
            atomicAdd(&g_sum_a2, (double)x4);
            __threadfence();
            unsigned int r = atomicAdd(&g_arrive, 1u);
            is_last = (r == (unsigned int)(NBLOCKS - 1));
        }
    }
    __syncthreads();
    if (!is_last) return;

    // ===================== finalize: both arrays concurrent =================
    double sp1 = __ldcg(&g_sum_p1);
    double sp2 = __ldcg(&g_sum_p2);
    double sa1 = __ldcg(&g_sum_a1);
    double sa2 = __ldcg(&g_sum_a2);

    int half    = tid >> 9;          // 0/1 == array index
    int htid    = tid & 511;
    int hwarp   = htid >> 5;         // 0..15
    int arr     = half;
    int binbase = htid << 2;         // 4 bins per thread (32B-aligned span)

    // ---- trip 1: vectorized hist load (2x LDG.128), decode into registers
    unsigned int cnt[4];
    float        wsm[4];
    {
        const ulonglong2* hp =
            reinterpret_cast<const ulonglong2*>(&g_hist[arr][binbase]);
        ulonglong2 v01 = __ldcg(&hp[0]);
        ulonglong2 v23 = __ldcg(&hp[1]);
        unsigned long long vv[4] = {v01.x, v01.y, v23.x, v23.y};
        #pragma unroll
        for (int j = 0; j < 4; j++) {
            unsigned int c = (unsigned int)(vv[j] >> 40);
            long long    lw = (long long)(vv[j] & HIST_MASK)
                            - (long long)c * W_BIAS;
            cnt[j] = c;
            wsm[j] = (float)lw * (1.0f / W_SCALE);
        }
        // reset hist now (fire-and-forget vector stores)
        ulonglong2* hw = reinterpret_cast<ulonglong2*>(&g_hist[arr][binbase]);
        ulonglong2 z2; z2.x = 0ULL; z2.y = 0ULL;
        hw[0] = z2;
        hw[1] = z2;
    }

    // ---- fused level-1 select + suffix-weight (2 barriers)
    unsigned int lc = cnt[0] + cnt[1] + cnt[2] + cnt[3];
    float        lw = wsm[0] + wsm[1] + wsm[2] + wsm[3];
    unsigned int ic = lc; float iw = lw;
    #pragma unroll
    for (int o = 1; o < 32; o <<= 1) {
        unsigned int tc = __shfl_up_sync(0xffffffffu, ic, o);
        float        tw = __shfl_up_sync(0xffffffffu, iw, o);
        if (lane >= o) { ic += tc; iw += tw; }
    }
    if (lane == 31) { wt_c[half][hwarp] = ic; wt_w[half][hwarp] = iw; }
    __syncthreads();

    unsigned int woff_c = 0; float woff_w = 0.f, total_w = 0.f;
    #pragma unroll
    for (int w2 = 0; w2 < 16; w2++) {
        unsigned int cc = wt_c[half][w2];
        float        ww = wt_w[half][w2];
        if (w2 < hwarp) { woff_c += cc; woff_w += ww; }
        total_w += ww;
    }
    unsigned int ex  = woff_c + (ic - lc);
    float        exw = woff_w + (iw - lw);
    unsigned int K   = arr ? K2 : K1;
    {
        unsigned int c = ex; float wp = exw;
        #pragma unroll
        for (int j = 0; j < 4; j++) {
            if (K >= c && K < c + cnt[j]) {
                d0_sh[half]  = (unsigned int)(binbase + j);
                kin_sh[half] = K - c;
                suf_sh[half] = total_w - (wp + wsm[j]);
                nc_sh[half]  = cnt[j];
                ovf_sh[half] = (cnt[j] > SMALL) ? 1u : 0u;
            }
            c += cnt[j]; wp += wsm[j];
        }
    }
    __syncthreads();

    if (!(ovf_sh[0] | ovf_sh[1])) {
        // =============== fast path: small-set median, halves concurrent ====
        unsigned int d0  = d0_sh[half];
        unsigned int kin = kin_sh[half];
        unsigned int nc  = nc_sh[half];
        size_t slotbase = (size_t)(((unsigned)arr << 11) | d0) * CAP;

        // trip 2: bucket data (one element per thread; nc <= 512)
        if (htid < (int)nc) {
            uint2 kv = __ldcg(&g_bkt[slotbase + htid]);
            sk[half][htid] = kv.x;
            sw[half][htid] = __uint_as_float(kv.y);
        }
        __syncthreads();
        if (htid < (int)nc) {
            unsigned int mykey = sk[half][htid];
            unsigned int less = 0, eq = 0;
            for (unsigned int j = 0; j < nc; j++) {
                unsigned int kj = sk[half][j];
                less += (kj < mykey);
                eq   += (kj == mykey);
            }
            if (less <= kin && kin < less + eq) mkey_sh[half] = mykey;
        }
        __syncthreads();
        unsigned int mkey = mkey_sh[half];
        float s = (htid < (int)nc && sk[half][htid] >= mkey) ? sw[half][htid] : 0.f;
        #pragma unroll
        for (int o = 16; o; o >>= 1) s += __shfl_down_sync(0xffffffffu, s, o);
        if (lane == 0) wt_w[half][hwarp] = s;
        __syncthreads();
        if (htid == 0) {
            float tsum = 0.f;
            #pragma unroll
            for (int j = 0; j < 16; j++) tsum += wt_w[half][j];
            S_sh[half] = suf_sh[half] + tsum;
        }
    } else {
        // =============== fallback: recompute from inputs (block-wide) ======
        __syncthreads();
        for (int a2 = 0; a2 < 2; a2++) {
            unsigned int fd0 = d0_sh[a2];
            int n = a2 ? N2 : N1;
            const float* am = a2 ? am2 : am1;
            if (tid == 0) k_sh = kin_sh[a2];
            for (int b = tid; b < 2048; b += 1024) fb_hist[b] = 0u;
            __syncthreads();
            for (int j = tid; j < n; j += 1024) {
                unsigned int kk = mono(__float_as_uint(regather(a2, j, c2, c3)));
                if ((kk >> 21) == fd0) atomicAdd(&fb_hist[(kk >> 10) & 2047u], 1u);
            }
            __syncthreads();
            unsigned int d1 = block_select(fb_hist, 2048, warpbuf, &k_sh, &sel_sh);
            unsigned int p21 = (fd0 << 11) | d1;
            fb_hist[tid] = 0u;
            __syncthreads();
            for (int j = tid; j < n; j += 1024) {
                unsigned int kk = mono(__float_as_uint(regather(a2, j, c2, c3)));
                if ((kk >> 10) == p21) atomicAdd(&fb_hist[kk & 1023u], 1u);
            }
            __syncthreads();
            unsigned int d2 = block_select(fb_hist, 1024, warpbuf, &k_sh, &sel_sh);
            unsigned int mkey = (p21 << 10) | d2;
            float s = 0.f;
            for (int j = tid; j < n; j += 1024) {
                unsigned int kk = mono(__float_as_uint(regather(a2, j, c2, c3)));
                if ((kk >> 21) == fd0 && kk >= mkey) s += 1.0f - 2.0f * am[j];
            }
            s = block_sum(s, redf);
            if (tid == 0) S_sh[a2] = suf_sh[a2] + s;
            __syncthreads();
        }
    }
    __syncthreads();

    // ===================== output + remaining state reset ===================
    if (tid == 0) {
        double p = (sqrt(sp1) + sqrt(sp2)) * (1.0 / 38400.0);
        double q1sq = sa1 + (double)S_sh[0];
        double q2sq = sa2 + (double)S_sh[1];
        double q = (sqrt(q1sq) + sqrt(q2sq)) * (1.0 / 384.0);
        out[0] = (float)p;
        out[1] = (float)q;
        g_sum_p1 = 0.0; g_sum_p2 = 0.0;
        g_sum_a1 = 0.0; g_sum_a2 = 0.0;
        g_arrive = 0u;
    }
}

// ---------------------------------------------------------------------------
extern "C" void kernel_launch(void* const* d_in, const int* in_sizes, int n_in,
                              void* d_out, int out_size)
{
    const float* c2  = (const float*)d_in[0];
    const float* c3  = (const float*)d_in[1];
    const float* vm1 = (const float*)d_in[2];
    const float* vm2 = (const float*)d_in[3];
    const float* am1 = (const float*)d_in[4];
    const float* am2 = (const float*)d_in[5];
    float* out = (float*)d_out;

    fused_kernel<<<NBLOCKS, 1024>>>(c2, c3, vm1, vm2, am1, am2, out);
}